// round 16
// baseline (speedup 1.0000x reference)
#include <cuda_runtime.h>
#include <cuda_fp16.h>
#include <cstdint>
#include <math.h>

#define DD 800
#define NA_ 20000
#define NB_ 24000
#define NG_ 256

// ---- HMMA GEMM tiling (pure fp16 single pass, 4-stage) ----
#define BM 128
#define BN 160
#define BK 32
#define SA_ 0
#define SB_ 10240
#define STAGE_B 23040
#define SMEM_TOT (4 * STAGE_B)   // 92160

// ---------------------------------------------------------------------------
// Scratch layout (float offsets)
// ---------------------------------------------------------------------------
static constexpr size_t O_P1 = 0;             // [20000][2400] fp16 A|D|E half1
static constexpr size_t O_P2 = 48000000;      // fp16 half2
static constexpr size_t O_SMALL = 96000000;
static constexpr size_t O_TW   = 98400000;
static constexpr size_t O_THp  = 104800000;
static constexpr size_t O_TH2p = 120800000;
static constexpr size_t O_TEp  = 136800000;   // e fp16 plane; later sig1
static constexpr size_t O_TE2p = 156000000;   // e2 fp16 plane; later sig2
static constexpr size_t O_TUp  = 175200000;
__device__ __align__(1024) float g_scratch[176000000];

// ---------------------------------------------------------------------------
__device__ __forceinline__ uint32_t smem_u32(const void* p) {
    uint32_t a;
    asm("{ .reg .u64 t; cvta.to.shared.u64 t, %1; cvt.u32.u64 %0, t; }" : "=r"(a) : "l"(p));
    return a;
}
__device__ __forceinline__ void cp16(uint32_t saddr, const void* gaddr) {
    asm volatile("cp.async.cg.shared.global [%0], [%1], 16;" :: "r"(saddr), "l"(gaddr));
}
__device__ __forceinline__ void cp_commit() {
    asm volatile("cp.async.commit_group;" ::: "memory");
}
__device__ __forceinline__ void cp_wait2() {
    asm volatile("cp.async.wait_group 2;" ::: "memory");
}
__device__ __forceinline__ void cp_wait0() {
    asm volatile("cp.async.wait_group 0;" ::: "memory");
}
__device__ __forceinline__ void ldsm4(uint32_t* r, uint32_t addr) {
    asm volatile("ldmatrix.sync.aligned.m8n8.x4.shared.b16 {%0,%1,%2,%3}, [%4];"
                 : "=r"(r[0]), "=r"(r[1]), "=r"(r[2]), "=r"(r[3]) : "r"(addr));
}
__device__ __forceinline__ void mma16816(float* c, const uint32_t* a, const uint32_t* b) {
    asm volatile(
        "mma.sync.aligned.m16n8k16.row.col.f32.f16.f16.f32 "
        "{%0,%1,%2,%3}, {%4,%5,%6,%7}, {%8,%9}, {%0,%1,%2,%3};"
        : "+f"(c[0]), "+f"(c[1]), "+f"(c[2]), "+f"(c[3])
        : "r"(a[0]), "r"(a[1]), "r"(a[2]), "r"(a[3]), "r"(b[0]), "r"(b[1]));
}

// ---------------------------------------------------------------------------
// fp16 HMMA GEMM, z-batched pair.
// MODE 0: store fp32 acc+bias
// MODE 3: C = acc+bias + Ah[i0]+Ah[i1]+Cu[g] (bond fuse), BN stats.
//         z==2 slice performs the cross-gate conversion (sg0/sg1 = T1/T2 dests).
// MODE 4: store fp16 acc+bias; extra mtiles >= nmt compute the UFI projection
// MODE 5: fused atom update + mix, BN stats
// ---------------------------------------------------------------------------
template<int MODE>
__global__ __launch_bounds__(256, 2)
void hgemm_k(const __half* __restrict__ Ah0, const __half* __restrict__ Ah1,
             const __half* __restrict__ B0_, const __half* __restrict__ B1_,
             const float* __restrict__ bias0, const float* __restrict__ bias1,
             int bm0, int bm1, int bm2,
             void* __restrict__ C0, void* __restrict__ C1, int M, int ldc,
             const int* __restrict__ ba0, const int* __restrict__ ba1p,
             const int* __restrict__ bg0, const int* __restrict__ bg1p,
             const __half* __restrict__ P0g, const __half* __restrict__ P1g,
             const __half* __restrict__ CuB,
             float* __restrict__ st0, float* __restrict__ st1,
             const int* __restrict__ ab0_, const int* __restrict__ ab1_,
             const int* __restrict__ ag0_, const int* __restrict__ ag1_,
             const __half* __restrict__ sg0, const __half* __restrict__ sg1,
             const __half* __restrict__ AhU, const __half* __restrict__ BU,
             __half* __restrict__ CU, int bmu0, int bmu1, int bmu2)
{
    constexpr bool STATS = (MODE == 3 || MODE == 5);
    extern __shared__ char smem[];
    uint32_t sb = smem_u32(smem);
    int tid = threadIdx.x;
    int lid = tid & 31, wid = tid >> 5;
    int wm = wid & 3, wn = wid >> 2;
    int ntile = blockIdx.x, mtile = blockIdx.y, z = blockIdx.z;

    // MODE 3 z==2 slice: fused cross-gate + cast (grid-stride; no GEMM work)
    if (MODE == 3 && z == 2) {
        int nb = gridDim.x * gridDim.y;
        int bid = mtile * gridDim.x + ntile;
        const __half* Pa = P0g;
        const __half* Pb = P1g;
        __half* T1 = (__half*)sg0;   // dest for t1
        __half* T2 = (__half*)sg1;   // dest for t2
        int total = (NA_ * DD) / 4;
        for (int qi = bid * 256 + tid; qi < total; qi += nb * 256) {
            int i4 = qi * 4;
            int r = i4 / DD, c = i4 % DD;
            size_t po = (size_t)r * 2400 + 800 + c;
            float2 d1a = __half22float2(*(const __half2*)(Pa + po));
            float2 d1b = __half22float2(*(const __half2*)(Pa + po + 2));
            float2 d2a = __half22float2(*(const __half2*)(Pb + po));
            float2 d2b = __half22float2(*(const __half2*)(Pb + po + 2));
            float4 t1v, t2v;
            float f;
            f = 1.f / (fabsf(d1a.x - d2a.x) + 1.f); t1v.x = f * d1a.x; t2v.x = f * d2a.x;
            f = 1.f / (fabsf(d1a.y - d2a.y) + 1.f); t1v.y = f * d1a.y; t2v.y = f * d2a.y;
            f = 1.f / (fabsf(d1b.x - d2b.x) + 1.f); t1v.z = f * d1b.x; t2v.z = f * d2b.x;
            f = 1.f / (fabsf(d1b.y - d2b.y) + 1.f); t1v.w = f * d1b.y; t2v.w = f * d2b.y;
            __half2 a = __floats2half2_rn(t1v.x, t1v.y);
            __half2 b = __floats2half2_rn(t1v.z, t1v.w);
            *(uint2*)((unsigned short*)T1 + i4) = make_uint2(*(uint32_t*)&a, *(uint32_t*)&b);
            a = __floats2half2_rn(t2v.x, t2v.y);
            b = __floats2half2_rn(t2v.z, t2v.w);
            *(uint2*)((unsigned short*)T2 + i4) = make_uint2(*(uint32_t*)&a, *(uint32_t*)&b);
        }
        return;
    }

    // UFI fold (MODE 4 only): last two mtiles compute u-projection (z=0 only)
    int uf = 0, mt = mtile, Mloc = M;
    if (MODE == 4 && AhU != nullptr) {
        int nmt = (M + BM - 1) / BM;
        if (mtile >= nmt) {
            if (z) return;
            uf = 1;
            mt = mtile - nmt;
            Mloc = NG_;
        }
    }

    const __half* Ahp = uf ? AhU : (z ? Ah1 : Ah0);
    const __half* Bp  = uf ? BU  : (z ? B1_ : B0_);
    const float* bias = z ? bias1 : bias0;

    int arow[2], acol[2];
    uint32_t asoff[2];
#pragma unroll
    for (int t = 0; t < 2; t++) {
        int q = tid + t * 256;
        int r = q >> 2, c = q & 3;
        arow[t] = min(mt * BM + r, Mloc - 1);
        acol[t] = c * 8;
        asoff[t] = r * 80 + c * 16;
    }
    int brow[3], bcol[3];
    uint32_t bsoff[3];
#pragma unroll
    for (int t = 0; t < 3; t++) {
        int q = tid + t * 256;
        int r = q >> 2, c = q & 3;
        brow[t] = ntile * BN + r;
        bcol[t] = c * 8;
        bsoff[t] = r * 80 + c * 16;
    }
    bool b3 = (tid < 128);

    auto load_stage = [&](int s, int kc) {
        uint32_t st = sb + s * STAGE_B;
        int k0 = kc * BK;
#pragma unroll
        for (int t = 0; t < 2; t++)
            cp16(st + SA_ + asoff[t], Ahp + (size_t)arow[t] * DD + k0 + acol[t]);
#pragma unroll
        for (int t = 0; t < 2; t++)
            cp16(st + SB_ + bsoff[t], Bp + (size_t)brow[t] * DD + k0 + bcol[t]);
        if (b3)
            cp16(st + SB_ + bsoff[2], Bp + (size_t)brow[2] * DD + k0 + bcol[2]);
    };

    float acc[2][10][4];
#pragma unroll
    for (int i = 0; i < 2; i++)
#pragma unroll
        for (int j = 0; j < 10; j++)
#pragma unroll
            for (int k = 0; k < 4; k++) acc[i][j][k] = 0.f;

    uint32_t aswz = (lid & 15) * 80 + (lid >> 4) * 16;
    uint32_t bswz = ((lid & 7) + ((lid & 16) ? 8 : 0)) * 80 + ((lid >> 3) & 1) * 16;
    uint32_t a_base = (wm * 32) * 80 + aswz;
    uint32_t b_base = (wn * 80) * 80 + bswz;

    load_stage(0, 0); cp_commit();
    load_stage(1, 1); cp_commit();
    load_stage(2, 2); cp_commit();

#pragma unroll 1
    for (int kc = 0; kc < 25; kc++) {
        int s = kc & 3;
        cp_wait2();
        __syncthreads();
        uint32_t st = sb + s * STAGE_B;
#pragma unroll
        for (int k16 = 0; k16 < 2; k16++) {
            uint32_t aH[2][4];
            ldsm4(aH[0], st + SA_ + a_base + k16 * 32);
            ldsm4(aH[1], st + SA_ + a_base + 16 * 80 + k16 * 32);
#pragma unroll
            for (int g = 0; g < 5; g++) {
                uint32_t bH[4];
                ldsm4(bH, st + SB_ + b_base + g * 16 * 80 + k16 * 32);
                mma16816(acc[0][2 * g],     aH[0], bH);
                mma16816(acc[0][2 * g + 1], aH[0], bH + 2);
                mma16816(acc[1][2 * g],     aH[1], bH);
                mma16816(acc[1][2 * g + 1], aH[1], bH + 2);
            }
        }
        if (kc + 3 < 25) load_stage((kc + 3) & 3, kc + 3);
        cp_commit();
    }

    // ---------------- epilogue ----------------
    cp_wait0();
    __syncthreads();
    float* smst = (float*)smem;
    if (STATS) {
        for (int i = tid; i < 320; i += 256) smst[i] = 0.f;
        __syncthreads();
    }

    int bseg = ntile / 5;
    int bsel = uf ? (bseg == 0 ? bmu0 : bseg == 1 ? bmu1 : bmu2)
                  : (bseg == 0 ? bm0 : bseg == 1 ? bm1 : bm2);
    const float* bp = bias + bsel * 800 - bseg * 800;

    float* Cf  = (float*)(z ? C1 : C0);
    __half* Ch = uf ? CU : (__half*)(z ? C1 : C0);
    float* st = z ? st1 : st0;

    if (MODE == 5) {
        const int* AB  = z ? ab1_ : ab0_;
        const int* BAm = z ? ba1p : ba0;
        const int* AG  = z ? ag1_ : ag0_;
        const __half* SG = z ? sg1 : sg0;
        const __half* Pm = z ? P1g : P0g;
#pragma unroll
        for (int q = 0; q < 4; q++) {
            const int iq = q >> 1, half = q & 1;
            int r = mt * BM + wm * 32 + iq * 16 + half * 8 + (lid >> 2);
            bool ok = r < Mloc;
            int b0 = 0, b1 = 0, b2 = 0, b3i = 0, o0 = 0, o1 = 0, o2 = 0, o3 = 0, gg = 0;
            if (ok) {
                int4 bb = ((const int4*)AB)[r];
                b0 = bb.x; b1 = bb.y; b2 = bb.z; b3i = bb.w;
                int2 p;
                p = ((const int2*)BAm)[b0];  o0 = (p.x != r) ? p.x : p.y;
                p = ((const int2*)BAm)[b1];  o1 = (p.x != r) ? p.x : p.y;
                p = ((const int2*)BAm)[b2];  o2 = (p.x != r) ? p.x : p.y;
                p = ((const int2*)BAm)[b3i]; o3 = (p.x != r) ? p.x : p.y;
                gg = AG[r];
            }
#pragma unroll
            for (int j = 0; j < 10; j++) {
                int colloc = wn * 80 + j * 8 + (lid & 3) * 2;
                int col = ntile * 160 + colloc;
                float v0 = 0.f, v1 = 0.f;
                if (ok) {
                    float2 bv = *(const float2*)(bp + col);
                    float a0 = acc[iq][j][half * 2 + 0] + bv.x;
                    float a1 = acc[iq][j][half * 2 + 1] + bv.y;
                    float2 w0 = __half22float2(*(const __half2*)(SG + (size_t)b0 * DD + col));
                    float2 w1 = __half22float2(*(const __half2*)(SG + (size_t)b1 * DD + col));
                    float2 w2 = __half22float2(*(const __half2*)(SG + (size_t)b2 * DD + col));
                    float2 w3 = __half22float2(*(const __half2*)(SG + (size_t)b3i * DD + col));
                    float2 e0 = __half22float2(*(const __half2*)(Pm + (size_t)o0 * 2400 + 1600 + col));
                    float2 e1v = __half22float2(*(const __half2*)(Pm + (size_t)o1 * 2400 + 1600 + col));
                    float2 e2v = __half22float2(*(const __half2*)(Pm + (size_t)o2 * 2400 + 1600 + col));
                    float2 e3v = __half22float2(*(const __half2*)(Pm + (size_t)o3 * 2400 + 1600 + col));
                    float2 dh = __half22float2(*(const __half2*)(Pm + (size_t)r * 2400 + 800 + col));
                    float2 fu = __half22float2(*(const __half2*)(CuB + (size_t)gg * 2400 + 800 + col));
                    float num0 = w0.x * e0.x + w1.x * e1v.x + w2.x * e2v.x + w3.x * e3v.x;
                    float den0 = w0.x + w1.x + w2.x + w3.x + 1e-6f;
                    float num1 = w0.y * e0.y + w1.y * e1v.y + w2.y * e2v.y + w3.y * e3v.y;
                    float den1 = w0.y + w1.y + w2.y + w3.y + 1e-6f;
                    float h0 = dh.x + __fdividef(num0, den0) + fu.x;
                    float h1v = dh.y + __fdividef(num1, den1) + fu.y;
                    v0 = h0 * 0.8f + 0.2f * a0;
                    v1 = h1v * 0.8f + 0.2f * a1;
                    *(float2*)&Cf[(size_t)r * ldc + col] = make_float2(v0, v1);
                }
                float s0 = v0, s1 = v1, q0 = v0 * v0, q1 = v1 * v1;
#pragma unroll
                for (int d = 4; d < 32; d <<= 1) {
                    s0 += __shfl_xor_sync(0xFFFFFFFFu, s0, d);
                    s1 += __shfl_xor_sync(0xFFFFFFFFu, s1, d);
                    q0 += __shfl_xor_sync(0xFFFFFFFFu, q0, d);
                    q1 += __shfl_xor_sync(0xFFFFFFFFu, q1, d);
                }
                if (lid < 4) {
                    atomicAdd(&smst[colloc], s0);
                    atomicAdd(&smst[colloc + 1], s1);
                    atomicAdd(&smst[160 + colloc], q0);
                    atomicAdd(&smst[160 + colloc + 1], q1);
                }
            }
        }
    } else {
        const int* BA = z ? ba1p : ba0;
        const int* BG = z ? bg1p : bg0;
        const __half* Pg = z ? P1g : P0g;
        int rows[4];
        bool rok[4];
        const __half *pA0[4], *pA1[4], *pCu[4];
#pragma unroll
        for (int q = 0; q < 4; q++) {
            int i = q >> 1, half = q & 1;
            int r = mt * BM + wm * 32 + i * 16 + half * 8 + (lid >> 2);
            rows[q] = r;
            rok[q] = r < Mloc;
            if (MODE == 3 && rok[q]) {
                int2 bb = ((const int2*)BA)[r];
                int gg = BG[r];
                pA0[q] = Pg + (size_t)bb.x * 2400;
                pA1[q] = Pg + (size_t)bb.y * 2400;
                pCu[q] = CuB + (size_t)gg * 2400;
            }
        }
#pragma unroll
        for (int j = 0; j < 10; j++) {
            int colloc = wn * 80 + j * 8 + (lid & 3) * 2;
            int col = ntile * 160 + colloc;
            float2 bv = *(const float2*)(bp + col);
            float s0 = 0.f, s1 = 0.f, q0 = 0.f, q1 = 0.f;
#pragma unroll
            for (int q = 0; q < 4; q++) {
                if (!rok[q]) continue;
                int i = q >> 1, half = q & 1;
                float v0 = acc[i][j][half * 2 + 0] + bv.x;
                float v1 = acc[i][j][half * 2 + 1] + bv.y;
                if (MODE == 3) {
                    float2 a0v = __half22float2(*(const __half2*)(pA0[q] + col));
                    float2 a1v = __half22float2(*(const __half2*)(pA1[q] + col));
                    float2 cuv = __half22float2(*(const __half2*)(pCu[q] + col));
                    v0 += a0v.x + a1v.x + cuv.x;
                    v1 += a0v.y + a1v.y + cuv.y;
                }
                if (MODE == 4) {
                    *(__half2*)(Ch + (size_t)rows[q] * ldc + col) = __floats2half2_rn(v0, v1);
                } else {
                    *(float2*)&Cf[(size_t)rows[q] * ldc + col] = make_float2(v0, v1);
                }
                if (STATS) {
                    s0 += v0; q0 += v0 * v0;
                    s1 += v1; q1 += v1 * v1;
                }
            }
            if (STATS) {
#pragma unroll
                for (int d = 4; d < 32; d <<= 1) {
                    s0 += __shfl_xor_sync(0xFFFFFFFFu, s0, d);
                    s1 += __shfl_xor_sync(0xFFFFFFFFu, s1, d);
                    q0 += __shfl_xor_sync(0xFFFFFFFFu, q0, d);
                    q1 += __shfl_xor_sync(0xFFFFFFFFu, q1, d);
                }
                if (lid < 4) {
                    atomicAdd(&smst[colloc], s0);
                    atomicAdd(&smst[colloc + 1], s1);
                    atomicAdd(&smst[160 + colloc], q0);
                    atomicAdd(&smst[160 + colloc + 1], q1);
                }
            }
        }
    }
    if (STATS) {
        __syncthreads();
        for (int i = tid; i < 160; i += 256) {
            atomicAdd(&st[ntile * 160 + i], smst[i]);
            atomicAdd(&st[4000 + ntile * 160 + i], smst[160 + i]);
        }
    }
}

// ---------------------------------------------------------------------------
// conversions
// ---------------------------------------------------------------------------
__global__ void conv_all_k(const float* __restrict__ h, const float* __restrict__ h2,
                           const float* __restrict__ e, const float* __restrict__ e2,
                           __half* __restrict__ th, __half* __restrict__ th2,
                           __half* __restrict__ te, __half* __restrict__ te2)
{
    int z = blockIdx.y;
    const float* A = (z == 0) ? h : (z == 1) ? h2 : (z == 2) ? e : e2;
    __half* T = (z == 0) ? th : (z == 1) ? th2 : (z == 2) ? te : te2;
    int n = (z < 2) ? NA_ * DD : NB_ * DD;
    int i4 = (blockIdx.x * blockDim.x + threadIdx.x) * 4;
    if (i4 >= n) return;
    float4 v = *(const float4*)(A + i4);
    __half2 a = __floats2half2_rn(v.x, v.y);
    __half2 b = __floats2half2_rn(v.z, v.w);
    *(uint2*)((unsigned short*)T + i4) = make_uint2(*(uint32_t*)&a, *(uint32_t*)&b);
}
__global__ void zero_k(float* p, int n) {
    int i = blockIdx.x * blockDim.x + threadIdx.x;
    if (i < n) p[i] = 0.f;
}
// y=0..3 counts, y=4 u conversion (AFTER zero_k — no race on cnts)
__global__ void setup_k(const int* __restrict__ ag1, const int* __restrict__ bg1,
                        const int* __restrict__ ag2, const int* __restrict__ bg2,
                        float* __restrict__ cnts,
                        const float* __restrict__ u, __half* __restrict__ tup)
{
    int y = blockIdx.y;
    int i = blockIdx.x * blockDim.x + threadIdx.x;
    if (y < 4) {
        const int* s = (y == 0) ? ag1 : (y == 1) ? bg1 : (y == 2) ? ag2 : bg2;
        int n = (y & 1) ? NB_ : NA_;
        if (i < n) atomicAdd(&cnts[y * 256 + s[i]], 1.0f);
    } else {
        int i4 = i * 4;
        if (i4 >= NG_ * DD) return;
        float4 v = *(const float4*)(u + i4);
        __half2 a = __floats2half2_rn(v.x, v.y);
        __half2 b = __floats2half2_rn(v.z, v.w);
        *(uint2*)((unsigned short*)tup + i4) = make_uint2(*(uint32_t*)&a, *(uint32_t*)&b);
    }
}

// weight transpose -> fp16 plane, packed groups
__global__ void conv_w_k(const float* __restrict__ Ws, __half* __restrict__ TW)
{
    static const int BASE[10]   = {0, 1920000, 2560000, 0, 0, 2560000, 4480000, 5120000, 2560000, 5760000};
    static const int ROWOFF[10] = {0, 0, 0, 800, 1600, 800, 0, 0, 1600, 0};
    __shared__ float t[32][33];
    int wi = blockIdx.z;
    const float* W = Ws + (size_t)wi * (DD * DD);
    __half* hi = TW + BASE[wi] + (size_t)ROWOFF[wi] * DD;
    int tx = threadIdx.x, ty = threadIdx.y;
    int kb = blockIdx.y * 32, nb = blockIdx.x * 32;
#pragma unroll
    for (int r = 0; r < 4; r++)
        t[ty + r * 8][tx] = W[(size_t)(kb + ty + r * 8) * DD + nb + tx];
    __syncthreads();
#pragma unroll
    for (int r = 0; r < 4; r++) {
        int nrow = nb + ty + r * 8;
        int kcol = kb + tx;
        hi[(size_t)nrow * DD + kcol] = __float2half_rn(t[tx][ty + r * 8]);
    }
}

// ---------------------------------------------------------------------------
// fused BN(prep+apply) + relu + segment-sum (+ optional fp16 sigmoid emit), z-pair
__global__ void bnseg2_k(float* __restrict__ X0, float* __restrict__ X1, int M,
                         const int* __restrict__ seg0, const int* __restrict__ seg1,
                         const float* __restrict__ sum, const float* __restrict__ sumsq,
                         const float* __restrict__ gamma, const float* __restrict__ beta,
                         float Rf,
                         float* __restrict__ ssum0, float* __restrict__ ssum1,
                         __half* __restrict__ sg0, __half* __restrict__ sg1)
{
    extern __shared__ float sm[];
    int zz = blockIdx.z;
    float* X = zz ? X1 : X0;
    const int* seg = zz ? seg1 : seg0;
    float* ssum = zz ? ssum1 : ssum0;
    __half* sigout = zz ? sg1 : sg0;
    int c0 = blockIdx.x * 64;
    int cl = threadIdx.x & 63;
    int col = c0 + cl;
    int rg = threadIdx.x >> 6;
    for (int i = threadIdx.x; i < 16384; i += 256) sm[i] = 0.f;
    __syncthreads();
    bool ok = col < DD;
    float sc = 0.f, sh = 0.f;
    if (ok) {
        float m = sum[zz * 800 + col] / Rf;
        float v = sumsq[zz * 800 + col] / Rf - m * m;
        sc = gamma[col] * rsqrtf(v + 1e-5f);
        sh = beta[col] - m * sc;
    }
    int chunk = (M + gridDim.y - 1) / gridDim.y;
    int r0 = blockIdx.y * chunk;
    int r1 = min(r0 + chunk, M);
    for (int r = r0 + rg; r < r1; r += 4) {
        int g = seg[r];
        if (ok) {
            float y = fmaxf(fmaf(X[(size_t)r * DD + col], sc, sh), 0.f);
            X[(size_t)r * DD + col] = y;
            if (sigout) {
                float s = __fdividef(1.f, 1.f + __expf(-y));
                sigout[(size_t)r * DD + col] = __float2half_rn(s);
            }
            atomicAdd(&sm[g * 64 + cl], y);
        }
    }
    __syncthreads();
    for (int i = threadIdx.x; i < 16384; i += 256) {
        int g = i >> 6;
        int c = c0 + (i & 63);
        float v = sm[i];
        if (c < DD && v != 0.f) atomicAdd(&ssum[g * DD + c], v);
    }
}
__global__ void meanprep_k(const float* __restrict__ ssum, const float* __restrict__ cnts,
                           __half* __restrict__ mH, __half* __restrict__ mE)
{
    int i4 = (blockIdx.x * blockDim.x + threadIdx.x) * 4;
    if (i4 >= NG_ * DD) return;
    int g = i4 / DD;
    float cA1 = fmaxf(cnts[g], 1.f),       cA2 = fmaxf(cnts[512 + g], 1.f);
    float cB1 = fmaxf(cnts[256 + g], 1.f), cB2 = fmaxf(cnts[768 + g], 1.f);
    const float* sh1 = ssum + i4;
    const float* se1 = ssum + 204800 + i4;
    const float* sh2 = ssum + 409600 + i4;
    const float* se2 = ssum + 614400 + i4;
    float4 vh, ve;
    vh.x = sh1[0] / cA1 + sh2[0] / cA2;  ve.x = se1[0] / cB1 + se2[0] / cB2;
    vh.y = sh1[1] / cA1 + sh2[1] / cA2;  ve.y = se1[1] / cB1 + se2[1] / cB2;
    vh.z = sh1[2] / cA1 + sh2[2] / cA2;  ve.z = se1[2] / cB1 + se2[2] / cB2;
    vh.w = sh1[3] / cA1 + sh2[3] / cA2;  ve.w = se1[3] / cB1 + se2[3] / cB2;
    __half2 a = __floats2half2_rn(vh.x, vh.y);
    __half2 b = __floats2half2_rn(vh.z, vh.w);
    *(uint2*)((unsigned short*)mH + i4) = make_uint2(*(uint32_t*)&a, *(uint32_t*)&b);
    a = __floats2half2_rn(ve.x, ve.y);
    b = __floats2half2_rn(ve.z, ve.w);
    *(uint2*)((unsigned short*)mE + i4) = make_uint2(*(uint32_t*)&a, *(uint32_t*)&b);
}
// fused: un = P6+P7+Iu+ind-bias, column stats, then BN+relu applied in-block
__global__ void ucombfinal_k(float* __restrict__ un, const float* __restrict__ P6,
                             const float* __restrict__ P7, const __half* __restrict__ UFIh,
                             const float* __restrict__ cnts, const float* __restrict__ bs,
                             const float* __restrict__ gamma, const float* __restrict__ beta)
{
    __shared__ float ssm[8][32], sqm[8][32];
    __shared__ float sS[32], sQ[32];
    int cl = threadIdx.x & 31, rg = threadIdx.x >> 5;
    int col = blockIdx.x * 32 + cl;
    bool ok = col < DD;
    float s = 0.f, q = 0.f;
    if (ok) {
        float b6 = bs[6 * 800 + col], b7 = bs[7 * 800 + col];
        for (int g = rg; g < NG_; g += 8) {
            float indA = (cnts[g] > 0.f ? 1.f : 0.f) + (cnts[512 + g] > 0.f ? 1.f : 0.f);
            float indB = (cnts[256 + g] > 0.f ? 1.f : 0.f) + (cnts[768 + g] > 0.f ? 1.f : 0.f);
            float v = P6[(size_t)g * DD + col] + P7[(size_t)g * DD + col]
                    + __half2float(UFIh[(size_t)g * 2400 + 1600 + col])
                    + b6 * indA + b7 * indB;
            un[(size_t)g * DD + col] = v;
            s += v; q += v * v;
        }
    }
    ssm[rg][cl] = s; sqm[rg][cl] = q;
    __syncthreads();
    if (rg == 0) {
        float S = 0.f, Q = 0.f;
#pragma unroll
        for (int r = 0; r < 8; r++) { S += ssm[r][cl]; Q += sqm[r][cl]; }
        sS[cl] = S; sQ[cl] = Q;
    }
    __syncthreads();
    if (ok) {
        float m = sS[cl] / (float)NG_;
        float v = sQ[cl] / (float)NG_ - m * m;
        float sc = gamma[col] * rsqrtf(v + 1e-5f);
        float sh = beta[col] - m * sc;
        for (int g = rg; g < NG_; g += 8) {
            float y = un[(size_t)g * DD + col];
            un[(size_t)g * DD + col] = fmaxf(fmaf(y, sc, sh), 0.f);
        }
    }
}

// ---------------------------------------------------------------------------
extern "C" void kernel_launch(void* const* d_in, const int* in_sizes, int n_in,
                              void* d_out, int out_size)
{
    const float* h   = (const float*)d_in[0];
    const float* e   = (const float*)d_in[1];
    const float* h2  = (const float*)d_in[2];
    const float* e2  = (const float*)d_in[3];
    const float* u   = (const float*)d_in[4];
    const float* Ws  = (const float*)d_in[5];
    const float* bs  = (const float*)d_in[6];
    const float* gam = (const float*)d_in[7];
    const float* bet = (const float*)d_in[8];
    const int* ba1 = (const int*)d_in[9];
    const int* ab1 = (const int*)d_in[10];
    const int* ag1 = (const int*)d_in[11];
    const int* bg1 = (const int*)d_in[12];
    const int* ba2 = (const int*)d_in[13];
    const int* ab2 = (const int*)d_in[14];
    const int* ag2 = (const int*)d_in[15];
    const int* bg2 = (const int*)d_in[16];

    float* out = (float*)d_out;
    float* h1n = out;
    float* e1n = out + 16000000;
    float* h2n = out + 35200000;
    float* e2n = out + 51200000;
    float* un  = out + 70400000;

    float* sp = nullptr;
    cudaGetSymbolAddress((void**)&sp, g_scratch);

    __half* P1 = (__half*)(sp + O_P1);
    __half* P2 = (__half*)(sp + O_P2);
    float* SM  = sp + O_SMALL;
    __half* UFIh = (__half*)SM;               // [256][2400] fp16
    float* ssum  = SM + 614400;
    float* cnts  = SM + 1433600;
    float* bnsum = SM + 1434624;
    float* bnsq  = SM + 1438624;
    float* zbias = SM + 1442624;
    __half* mH = (__half*)(SM + 1456224);
    __half* mE = (__half*)(SM + 1661024);
    float* P6 = SM + 1865824;
    float* P7 = SM + 2070624;

    __half* tw   = (__half*)(sp + O_TW);
    __half* thp  = (__half*)(sp + O_THp);
    __half* th2p = (__half*)(sp + O_TH2p);
    __half* tep  = (__half*)(sp + O_TEp);
    __half* te2p = (__half*)(sp + O_TE2p);
    __half* tup  = (__half*)(sp + O_TUp);
    __half* sig1 = tep;
    __half* sig2 = te2p;

    __half* TADE = tw + 0;
    __half* TB1  = tw + 1920000;
    __half* TUFI = tw + 2560000;
    __half* TG   = tw + 4480000;
    __half* TH7  = tw + 5120000;
    __half* TW9  = tw + 5760000;

    const int NU = NG_ * DD;

    cudaFuncSetAttribute(hgemm_k<0>, cudaFuncAttributeMaxDynamicSharedMemorySize, SMEM_TOT);
    cudaFuncSetAttribute(hgemm_k<3>, cudaFuncAttributeMaxDynamicSharedMemorySize, SMEM_TOT);
    cudaFuncSetAttribute(hgemm_k<4>, cudaFuncAttributeMaxDynamicSharedMemorySize, SMEM_TOT);
    cudaFuncSetAttribute(hgemm_k<5>, cudaFuncAttributeMaxDynamicSharedMemorySize, SMEM_TOT);
    cudaFuncSetAttribute(bnseg2_k, cudaFuncAttributeMaxDynamicSharedMemorySize, 65536);

    #define NIL6 nullptr, nullptr, nullptr, nullptr, nullptr, nullptr
    #define NILU nullptr, nullptr, nullptr, 0, 0, 0

    // setup + conversions (zero BEFORE counts — no race)
    zero_k<<<(829024 + 255) / 256, 256>>>(ssum, 829024);
    conv_all_k<<<dim3(18750, 4), 256>>>(h, h2, e, e2, thp, th2p, tep, te2p);
    setup_k<<<dim3(200, 5), 256>>>(ag1, bg1, ag2, bg2, cnts, u, tup);
    conv_w_k<<<dim3(25, 25, 10), dim3(32, 8)>>>(Ws, tw);

    // ADE projections -> fp16 P, with UFI fold (mtiles 157,158)
    hgemm_k<4><<<dim3(15, 159, 2), 256, SMEM_TOT>>>(
        thp, th2p, TADE, TADE, bs, bs, 0, 3, 4,
        P1, P2, NA_, 2400,
        nullptr, nullptr, nullptr, nullptr, nullptr, nullptr, nullptr, nullptr, nullptr, NIL6,
        tup, TUFI, UFIh, 2, 5, 8);

    // e-projection + fused bond update + BN stats; z==2 slice = cross-gate conv
    hgemm_k<3><<<dim3(5, 188, 3), 256, SMEM_TOT>>>(
        tep, te2p, TB1, TB1, bs, bs, 1, 1, 1,
        e1n, e2n, NB_, 800,
        ba1, ba2, bg1, bg2, P1, P2, UFIh,
        bnsum + 0, bnsum + 800,
        nullptr, nullptr, nullptr, nullptr, thp, th2p, NILU);

    // BN(e) apply (prep inline) + segsum + sigmoid emit
    bnseg2_k<<<dim3(13, 12, 2), 256, 65536>>>(e1n, e2n, NB_, bg1, bg2,
                                              bnsum + 0, bnsq + 0, gam, bet, (float)NB_,
                                              ssum + 204800, ssum + 614400, sig1, sig2);

    // fused atom update + cross mix + BN stats (MODE 5)
    hgemm_k<5><<<dim3(5, 157, 2), 256, SMEM_TOT>>>(
        th2p, thp, TW9, TW9, bs, bs, 9, 9, 9,
        h1n, h2n, NA_, 800,
        ba1, ba2, nullptr, nullptr, P1, P2, UFIh,
        bnsum + 1600, bnsum + 2400,
        ab1, ab2, ag1, ag2, sig1, sig2, NILU);

    // BN(h) apply (prep inline) + segsum
    bnseg2_k<<<dim3(13, 12, 2), 256, 65536>>>(h1n, h2n, NA_, ag1, ag2,
                                              bnsum + 1600, bnsq + 1600, gam + 800, bet + 800,
                                              (float)NA_,
                                              ssum + 0, ssum + 409600, nullptr, nullptr);

    // global readout on means
    meanprep_k<<<NU / 1024, 256>>>(ssum, cnts, mH, mE);
    hgemm_k<0><<<dim3(5, 2, 2), 256, SMEM_TOT>>>(
        mH, mE, TG, TH7, zbias, zbias, 0, 0, 0,
        P6, P7, NG_, 800,
        nullptr, nullptr, nullptr, nullptr, nullptr, nullptr, nullptr, nullptr, nullptr, NIL6, NILU);

    // fused combine + stats + BN + relu (single kernel, no extra launch)
    ucombfinal_k<<<25, 256>>>(un, P6, P7, UFIh, cnts, bs, gam + 1600, bet + 1600);
    #undef NIL6
    #undef NILU
}

// round 17
// speedup vs baseline: 1.0074x; 1.0074x over previous
#include <cuda_runtime.h>
#include <cuda_fp16.h>
#include <cstdint>
#include <math.h>

#define DD 800
#define NA_ 20000
#define NB_ 24000
#define NG_ 256

// ---- HMMA GEMM tiling (pure fp16 single pass, 4-stage) ----
#define BM 128
#define BN 160
#define BK 32
#define SA_ 0
#define SB_ 10240
#define STAGE_B 23040
#define SMEM_TOT (4 * STAGE_B)   // 92160

// ---------------------------------------------------------------------------
// Scratch layout (float offsets)
// ---------------------------------------------------------------------------
static constexpr size_t O_P1 = 0;             // [20000][2400] fp16 A|D|E half1
static constexpr size_t O_P2 = 48000000;      // fp16 half2
static constexpr size_t O_SMALL = 96000000;
static constexpr size_t O_TW   = 98400000;
static constexpr size_t O_THp  = 104800000;
static constexpr size_t O_TH2p = 120800000;
static constexpr size_t O_TEp  = 136800000;   // e fp16 plane; later sig1
static constexpr size_t O_TE2p = 156000000;   // e2 fp16 plane; later sig2
static constexpr size_t O_TUp  = 175200000;
__device__ __align__(1024) float g_scratch[176000000];

// ---------------------------------------------------------------------------
__device__ __forceinline__ uint32_t smem_u32(const void* p) {
    uint32_t a;
    asm("{ .reg .u64 t; cvta.to.shared.u64 t, %1; cvt.u32.u64 %0, t; }" : "=r"(a) : "l"(p));
    return a;
}
__device__ __forceinline__ void cp16(uint32_t saddr, const void* gaddr) {
    asm volatile("cp.async.cg.shared.global [%0], [%1], 16;" :: "r"(saddr), "l"(gaddr));
}
__device__ __forceinline__ void cp_commit() {
    asm volatile("cp.async.commit_group;" ::: "memory");
}
__device__ __forceinline__ void cp_wait2() {
    asm volatile("cp.async.wait_group 2;" ::: "memory");
}
__device__ __forceinline__ void cp_wait0() {
    asm volatile("cp.async.wait_group 0;" ::: "memory");
}
__device__ __forceinline__ void ldsm4(uint32_t* r, uint32_t addr) {
    asm volatile("ldmatrix.sync.aligned.m8n8.x4.shared.b16 {%0,%1,%2,%3}, [%4];"
                 : "=r"(r[0]), "=r"(r[1]), "=r"(r[2]), "=r"(r[3]) : "r"(addr));
}
__device__ __forceinline__ void mma16816(float* c, const uint32_t* a, const uint32_t* b) {
    asm volatile(
        "mma.sync.aligned.m16n8k16.row.col.f32.f16.f16.f32 "
        "{%0,%1,%2,%3}, {%4,%5,%6,%7}, {%8,%9}, {%0,%1,%2,%3};"
        : "+f"(c[0]), "+f"(c[1]), "+f"(c[2]), "+f"(c[3])
        : "r"(a[0]), "r"(a[1]), "r"(a[2]), "r"(a[3]), "r"(b[0]), "r"(b[1]));
}

// ---------------------------------------------------------------------------
// fp16 HMMA GEMM, z-batched pair.
// MODE 0: store fp32 acc+bias
// MODE 3: C = acc+bias + Ah[i0]+Ah[i1]+Cu[g] (bond fuse; fp16 gathers), BN stats
// MODE 4: store fp16 acc+bias; extra mtiles >= nmt compute the UFI projection
// MODE 5: fused atom update + mix, BN stats
// ---------------------------------------------------------------------------
template<int MODE>
__global__ __launch_bounds__(256, 2)
void hgemm_k(const __half* __restrict__ Ah0, const __half* __restrict__ Ah1,
             const __half* __restrict__ B0_, const __half* __restrict__ B1_,
             const float* __restrict__ bias0, const float* __restrict__ bias1,
             int bm0, int bm1, int bm2,
             void* __restrict__ C0, void* __restrict__ C1, int M, int ldc,
             const int* __restrict__ ba0, const int* __restrict__ ba1p,
             const int* __restrict__ bg0, const int* __restrict__ bg1p,
             const __half* __restrict__ P0g, const __half* __restrict__ P1g,
             const __half* __restrict__ CuB,
             float* __restrict__ st0, float* __restrict__ st1,
             const int* __restrict__ ab0_, const int* __restrict__ ab1_,
             const int* __restrict__ ag0_, const int* __restrict__ ag1_,
             const __half* __restrict__ sg0, const __half* __restrict__ sg1,
             const __half* __restrict__ AhU, const __half* __restrict__ BU,
             __half* __restrict__ CU, int bmu0, int bmu1, int bmu2)
{
    constexpr bool STATS = (MODE == 3 || MODE == 5);
    extern __shared__ char smem[];
    uint32_t sb = smem_u32(smem);
    int tid = threadIdx.x;
    int lid = tid & 31, wid = tid >> 5;
    int wm = wid & 3, wn = wid >> 2;
    int ntile = blockIdx.x, mtile = blockIdx.y, z = blockIdx.z;

    // UFI fold (MODE 4 only): last two mtiles compute u-projection (z=0 only)
    int uf = 0, mt = mtile, Mloc = M;
    if (MODE == 4 && AhU != nullptr) {
        int nmt = (M + BM - 1) / BM;
        if (mtile >= nmt) {
            if (z) return;
            uf = 1;
            mt = mtile - nmt;
            Mloc = NG_;
        }
    }

    const __half* Ahp = uf ? AhU : (z ? Ah1 : Ah0);
    const __half* Bp  = uf ? BU  : (z ? B1_ : B0_);
    const float* bias = z ? bias1 : bias0;

    int arow[2], acol[2];
    uint32_t asoff[2];
#pragma unroll
    for (int t = 0; t < 2; t++) {
        int q = tid + t * 256;
        int r = q >> 2, c = q & 3;
        arow[t] = min(mt * BM + r, Mloc - 1);
        acol[t] = c * 8;
        asoff[t] = r * 80 + c * 16;
    }
    int brow[3], bcol[3];
    uint32_t bsoff[3];
#pragma unroll
    for (int t = 0; t < 3; t++) {
        int q = tid + t * 256;
        int r = q >> 2, c = q & 3;
        brow[t] = ntile * BN + r;
        bcol[t] = c * 8;
        bsoff[t] = r * 80 + c * 16;
    }
    bool b3 = (tid < 128);

    auto load_stage = [&](int s, int kc) {
        uint32_t st = sb + s * STAGE_B;
        int k0 = kc * BK;
#pragma unroll
        for (int t = 0; t < 2; t++)
            cp16(st + SA_ + asoff[t], Ahp + (size_t)arow[t] * DD + k0 + acol[t]);
#pragma unroll
        for (int t = 0; t < 2; t++)
            cp16(st + SB_ + bsoff[t], Bp + (size_t)brow[t] * DD + k0 + bcol[t]);
        if (b3)
            cp16(st + SB_ + bsoff[2], Bp + (size_t)brow[2] * DD + k0 + bcol[2]);
    };

    float acc[2][10][4];
#pragma unroll
    for (int i = 0; i < 2; i++)
#pragma unroll
        for (int j = 0; j < 10; j++)
#pragma unroll
            for (int k = 0; k < 4; k++) acc[i][j][k] = 0.f;

    uint32_t aswz = (lid & 15) * 80 + (lid >> 4) * 16;
    uint32_t bswz = ((lid & 7) + ((lid & 16) ? 8 : 0)) * 80 + ((lid >> 3) & 1) * 16;
    uint32_t a_base = (wm * 32) * 80 + aswz;
    uint32_t b_base = (wn * 80) * 80 + bswz;

    load_stage(0, 0); cp_commit();
    load_stage(1, 1); cp_commit();
    load_stage(2, 2); cp_commit();

#pragma unroll 1
    for (int kc = 0; kc < 25; kc++) {
        int s = kc & 3;
        cp_wait2();
        __syncthreads();
        uint32_t st = sb + s * STAGE_B;
#pragma unroll
        for (int k16 = 0; k16 < 2; k16++) {
            uint32_t aH[2][4];
            ldsm4(aH[0], st + SA_ + a_base + k16 * 32);
            ldsm4(aH[1], st + SA_ + a_base + 16 * 80 + k16 * 32);
#pragma unroll
            for (int g = 0; g < 5; g++) {
                uint32_t bH[4];
                ldsm4(bH, st + SB_ + b_base + g * 16 * 80 + k16 * 32);
                mma16816(acc[0][2 * g],     aH[0], bH);
                mma16816(acc[0][2 * g + 1], aH[0], bH + 2);
                mma16816(acc[1][2 * g],     aH[1], bH);
                mma16816(acc[1][2 * g + 1], aH[1], bH + 2);
            }
        }
        if (kc + 3 < 25) load_stage((kc + 3) & 3, kc + 3);
        cp_commit();
    }

    // ---------------- epilogue ----------------
    cp_wait0();
    __syncthreads();
    float* smst = (float*)smem;
    if (STATS) {
        for (int i = tid; i < 320; i += 256) smst[i] = 0.f;
        __syncthreads();
    }

    int bseg = ntile / 5;
    int bsel = uf ? (bseg == 0 ? bmu0 : bseg == 1 ? bmu1 : bmu2)
                  : (bseg == 0 ? bm0 : bseg == 1 ? bm1 : bm2);
    const float* bp = bias + bsel * 800 - bseg * 800;

    float* Cf  = (float*)(z ? C1 : C0);
    __half* Ch = uf ? CU : (__half*)(z ? C1 : C0);
    float* st = z ? st1 : st0;

    if (MODE == 5) {
        const int* AB  = z ? ab1_ : ab0_;
        const int* BAm = z ? ba1p : ba0;
        const int* AG  = z ? ag1_ : ag0_;
        const __half* SG = z ? sg1 : sg0;
        const __half* Pm = z ? P1g : P0g;
#pragma unroll
        for (int q = 0; q < 4; q++) {
            const int iq = q >> 1, half = q & 1;
            int r = mt * BM + wm * 32 + iq * 16 + half * 8 + (lid >> 2);
            bool ok = r < Mloc;
            int b0 = 0, b1 = 0, b2 = 0, b3i = 0, o0 = 0, o1 = 0, o2 = 0, o3 = 0, gg = 0;
            if (ok) {
                int4 bb = ((const int4*)AB)[r];
                b0 = bb.x; b1 = bb.y; b2 = bb.z; b3i = bb.w;
                int2 p;
                p = ((const int2*)BAm)[b0];  o0 = (p.x != r) ? p.x : p.y;
                p = ((const int2*)BAm)[b1];  o1 = (p.x != r) ? p.x : p.y;
                p = ((const int2*)BAm)[b2];  o2 = (p.x != r) ? p.x : p.y;
                p = ((const int2*)BAm)[b3i]; o3 = (p.x != r) ? p.x : p.y;
                gg = AG[r];
            }
#pragma unroll
            for (int j = 0; j < 10; j++) {
                int colloc = wn * 80 + j * 8 + (lid & 3) * 2;
                int col = ntile * 160 + colloc;
                float v0 = 0.f, v1 = 0.f;
                if (ok) {
                    float2 bv = *(const float2*)(bp + col);
                    float a0 = acc[iq][j][half * 2 + 0] + bv.x;
                    float a1 = acc[iq][j][half * 2 + 1] + bv.y;
                    float2 w0 = __half22float2(*(const __half2*)(SG + (size_t)b0 * DD + col));
                    float2 w1 = __half22float2(*(const __half2*)(SG + (size_t)b1 * DD + col));
                    float2 w2 = __half22float2(*(const __half2*)(SG + (size_t)b2 * DD + col));
                    float2 w3 = __half22float2(*(const __half2*)(SG + (size_t)b3i * DD + col));
                    float2 e0 = __half22float2(*(const __half2*)(Pm + (size_t)o0 * 2400 + 1600 + col));
                    float2 e1v = __half22float2(*(const __half2*)(Pm + (size_t)o1 * 2400 + 1600 + col));
                    float2 e2v = __half22float2(*(const __half2*)(Pm + (size_t)o2 * 2400 + 1600 + col));
                    float2 e3v = __half22float2(*(const __half2*)(Pm + (size_t)o3 * 2400 + 1600 + col));
                    float2 dh = __half22float2(*(const __half2*)(Pm + (size_t)r * 2400 + 800 + col));
                    float2 fu = __half22float2(*(const __half2*)(CuB + (size_t)gg * 2400 + 800 + col));
                    float num0 = w0.x * e0.x + w1.x * e1v.x + w2.x * e2v.x + w3.x * e3v.x;
                    float den0 = w0.x + w1.x + w2.x + w3.x + 1e-6f;
                    float num1 = w0.y * e0.y + w1.y * e1v.y + w2.y * e2v.y + w3.y * e3v.y;
                    float den1 = w0.y + w1.y + w2.y + w3.y + 1e-6f;
                    float h0 = dh.x + __fdividef(num0, den0) + fu.x;
                    float h1v = dh.y + __fdividef(num1, den1) + fu.y;
                    v0 = h0 * 0.8f + 0.2f * a0;
                    v1 = h1v * 0.8f + 0.2f * a1;
                    *(float2*)&Cf[(size_t)r * ldc + col] = make_float2(v0, v1);
                }
                float s0 = v0, s1 = v1, q0 = v0 * v0, q1 = v1 * v1;
#pragma unroll
                for (int d = 4; d < 32; d <<= 1) {
                    s0 += __shfl_xor_sync(0xFFFFFFFFu, s0, d);
                    s1 += __shfl_xor_sync(0xFFFFFFFFu, s1, d);
                    q0 += __shfl_xor_sync(0xFFFFFFFFu, q0, d);
                    q1 += __shfl_xor_sync(0xFFFFFFFFu, q1, d);
                }
                if (lid < 4) {
                    atomicAdd(&smst[colloc], s0);
                    atomicAdd(&smst[colloc + 1], s1);
                    atomicAdd(&smst[160 + colloc], q0);
                    atomicAdd(&smst[160 + colloc + 1], q1);
                }
            }
        }
    } else {
        const int* BA = z ? ba1p : ba0;
        const int* BG = z ? bg1p : bg0;
        const __half* Pg = z ? P1g : P0g;
        int rows[4];
        bool rok[4];
        const __half *pA0[4], *pA1[4], *pCu[4];
#pragma unroll
        for (int q = 0; q < 4; q++) {
            int i = q >> 1, half = q & 1;
            int r = mt * BM + wm * 32 + i * 16 + half * 8 + (lid >> 2);
            rows[q] = r;
            rok[q] = r < Mloc;
            if (MODE == 3 && rok[q]) {
                int2 bb = ((const int2*)BA)[r];
                int gg = BG[r];
                pA0[q] = Pg + (size_t)bb.x * 2400;
                pA1[q] = Pg + (size_t)bb.y * 2400;
                pCu[q] = CuB + (size_t)gg * 2400;
            }
        }
#pragma unroll
        for (int j = 0; j < 10; j++) {
            int colloc = wn * 80 + j * 8 + (lid & 3) * 2;
            int col = ntile * 160 + colloc;
            float2 bv = *(const float2*)(bp + col);
            float s0 = 0.f, s1 = 0.f, q0 = 0.f, q1 = 0.f;
#pragma unroll
            for (int q = 0; q < 4; q++) {
                if (!rok[q]) continue;
                int i = q >> 1, half = q & 1;
                float v0 = acc[i][j][half * 2 + 0] + bv.x;
                float v1 = acc[i][j][half * 2 + 1] + bv.y;
                if (MODE == 3) {
                    float2 a0v = __half22float2(*(const __half2*)(pA0[q] + col));
                    float2 a1v = __half22float2(*(const __half2*)(pA1[q] + col));
                    float2 cuv = __half22float2(*(const __half2*)(pCu[q] + col));
                    v0 += a0v.x + a1v.x + cuv.x;
                    v1 += a0v.y + a1v.y + cuv.y;
                }
                if (MODE == 4) {
                    *(__half2*)(Ch + (size_t)rows[q] * ldc + col) = __floats2half2_rn(v0, v1);
                } else {
                    *(float2*)&Cf[(size_t)rows[q] * ldc + col] = make_float2(v0, v1);
                }
                if (STATS) {
                    s0 += v0; q0 += v0 * v0;
                    s1 += v1; q1 += v1 * v1;
                }
            }
            if (STATS) {
#pragma unroll
                for (int d = 4; d < 32; d <<= 1) {
                    s0 += __shfl_xor_sync(0xFFFFFFFFu, s0, d);
                    s1 += __shfl_xor_sync(0xFFFFFFFFu, s1, d);
                    q0 += __shfl_xor_sync(0xFFFFFFFFu, q0, d);
                    q1 += __shfl_xor_sync(0xFFFFFFFFu, q1, d);
                }
                if (lid < 4) {
                    atomicAdd(&smst[colloc], s0);
                    atomicAdd(&smst[colloc + 1], s1);
                    atomicAdd(&smst[160 + colloc], q0);
                    atomicAdd(&smst[160 + colloc + 1], q1);
                }
            }
        }
    }
    if (STATS) {
        __syncthreads();
        for (int i = tid; i < 160; i += 256) {
            atomicAdd(&st[ntile * 160 + i], smst[i]);
            atomicAdd(&st[4000 + ntile * 160 + i], smst[160 + i]);
        }
    }
}

// ---------------------------------------------------------------------------
// conversions
// ---------------------------------------------------------------------------
__global__ void conv_all_k(const float* __restrict__ h, const float* __restrict__ h2,
                           const float* __restrict__ e, const float* __restrict__ e2,
                           __half* __restrict__ th, __half* __restrict__ th2,
                           __half* __restrict__ te, __half* __restrict__ te2)
{
    int z = blockIdx.y;
    const float* A = (z == 0) ? h : (z == 1) ? h2 : (z == 2) ? e : e2;
    __half* T = (z == 0) ? th : (z == 1) ? th2 : (z == 2) ? te : te2;
    int n = (z < 2) ? NA_ * DD : NB_ * DD;
    int i4 = (blockIdx.x * blockDim.x + threadIdx.x) * 4;
    if (i4 >= n) return;
    float4 v = *(const float4*)(A + i4);
    __half2 a = __floats2half2_rn(v.x, v.y);
    __half2 b = __floats2half2_rn(v.z, v.w);
    *(uint2*)((unsigned short*)T + i4) = make_uint2(*(uint32_t*)&a, *(uint32_t*)&b);
}
__global__ void zero_k(float* p, int n) {
    int i = blockIdx.x * blockDim.x + threadIdx.x;
    if (i < n) p[i] = 0.f;
}
// y=0..3 counts, y=4 u conversion (AFTER zero_k — no race on cnts)
__global__ void setup_k(const int* __restrict__ ag1, const int* __restrict__ bg1,
                        const int* __restrict__ ag2, const int* __restrict__ bg2,
                        float* __restrict__ cnts,
                        const float* __restrict__ u, __half* __restrict__ tup)
{
    int y = blockIdx.y;
    int i = blockIdx.x * blockDim.x + threadIdx.x;
    if (y < 4) {
        const int* s = (y == 0) ? ag1 : (y == 1) ? bg1 : (y == 2) ? ag2 : bg2;
        int n = (y & 1) ? NB_ : NA_;
        if (i < n) atomicAdd(&cnts[y * 256 + s[i]], 1.0f);
    } else {
        int i4 = i * 4;
        if (i4 >= NG_ * DD) return;
        float4 v = *(const float4*)(u + i4);
        __half2 a = __floats2half2_rn(v.x, v.y);
        __half2 b = __floats2half2_rn(v.z, v.w);
        *(uint2*)((unsigned short*)tup + i4) = make_uint2(*(uint32_t*)&a, *(uint32_t*)&b);
    }
}

// weight transpose -> fp16 plane, packed groups
__global__ void conv_w_k(const float* __restrict__ Ws, __half* __restrict__ TW)
{
    static const int BASE[10]   = {0, 1920000, 2560000, 0, 0, 2560000, 4480000, 5120000, 2560000, 5760000};
    static const int ROWOFF[10] = {0, 0, 0, 800, 1600, 800, 0, 0, 1600, 0};
    __shared__ float t[32][33];
    int wi = blockIdx.z;
    const float* W = Ws + (size_t)wi * (DD * DD);
    __half* hi = TW + BASE[wi] + (size_t)ROWOFF[wi] * DD;
    int tx = threadIdx.x, ty = threadIdx.y;
    int kb = blockIdx.y * 32, nb = blockIdx.x * 32;
#pragma unroll
    for (int r = 0; r < 4; r++)
        t[ty + r * 8][tx] = W[(size_t)(kb + ty + r * 8) * DD + nb + tx];
    __syncthreads();
#pragma unroll
    for (int r = 0; r < 4; r++) {
        int nrow = nb + ty + r * 8;
        int kcol = kb + tx;
        hi[(size_t)nrow * DD + kcol] = __float2half_rn(t[tx][ty + r * 8]);
    }
}

// fused cross-gate + cast from fp16 P planes
__global__ void crossconv_k(const __half* __restrict__ P1, const __half* __restrict__ P2,
                            __half* __restrict__ T1, __half* __restrict__ T2)
{
    int i4 = (blockIdx.x * blockDim.x + threadIdx.x) * 4;
    if (i4 >= NA_ * DD) return;
    int r = i4 / DD, c = i4 % DD;
    size_t po = (size_t)r * 2400 + 800 + c;
    float2 d1a = __half22float2(*(const __half2*)(P1 + po));
    float2 d1b = __half22float2(*(const __half2*)(P1 + po + 2));
    float2 d2a = __half22float2(*(const __half2*)(P2 + po));
    float2 d2b = __half22float2(*(const __half2*)(P2 + po + 2));
    float4 t1v, t2v;
    float f;
    f = 1.f / (fabsf(d1a.x - d2a.x) + 1.f); t1v.x = f * d1a.x; t2v.x = f * d2a.x;
    f = 1.f / (fabsf(d1a.y - d2a.y) + 1.f); t1v.y = f * d1a.y; t2v.y = f * d2a.y;
    f = 1.f / (fabsf(d1b.x - d2b.x) + 1.f); t1v.z = f * d1b.x; t2v.z = f * d2b.x;
    f = 1.f / (fabsf(d1b.y - d2b.y) + 1.f); t1v.w = f * d1b.y; t2v.w = f * d2b.y;
    __half2 a = __floats2half2_rn(t1v.x, t1v.y);
    __half2 b = __floats2half2_rn(t1v.z, t1v.w);
    *(uint2*)((unsigned short*)T1 + i4) = make_uint2(*(uint32_t*)&a, *(uint32_t*)&b);
    a = __floats2half2_rn(t2v.x, t2v.y);
    b = __floats2half2_rn(t2v.z, t2v.w);
    *(uint2*)((unsigned short*)T2 + i4) = make_uint2(*(uint32_t*)&a, *(uint32_t*)&b);
}

// ---------------------------------------------------------------------------
// fused BN(prep+apply) + relu + segment-sum (+ optional fp16 sigmoid emit), z-pair
__global__ void bnseg2_k(float* __restrict__ X0, float* __restrict__ X1, int M,
                         const int* __restrict__ seg0, const int* __restrict__ seg1,
                         const float* __restrict__ sum, const float* __restrict__ sumsq,
                         const float* __restrict__ gamma, const float* __restrict__ beta,
                         float Rf,
                         float* __restrict__ ssum0, float* __restrict__ ssum1,
                         __half* __restrict__ sg0, __half* __restrict__ sg1)
{
    extern __shared__ float sm[];
    int zz = blockIdx.z;
    float* X = zz ? X1 : X0;
    const int* seg = zz ? seg1 : seg0;
    float* ssum = zz ? ssum1 : ssum0;
    __half* sigout = zz ? sg1 : sg0;
    int c0 = blockIdx.x * 64;
    int cl = threadIdx.x & 63;
    int col = c0 + cl;
    int rg = threadIdx.x >> 6;
    for (int i = threadIdx.x; i < 16384; i += 256) sm[i] = 0.f;
    __syncthreads();
    bool ok = col < DD;
    float sc = 0.f, sh = 0.f;
    if (ok) {
        float m = sum[zz * 800 + col] / Rf;
        float v = sumsq[zz * 800 + col] / Rf - m * m;
        sc = gamma[col] * rsqrtf(v + 1e-5f);
        sh = beta[col] - m * sc;
    }
    int chunk = (M + gridDim.y - 1) / gridDim.y;
    int r0 = blockIdx.y * chunk;
    int r1 = min(r0 + chunk, M);
    for (int r = r0 + rg; r < r1; r += 4) {
        int g = seg[r];
        if (ok) {
            float y = fmaxf(fmaf(X[(size_t)r * DD + col], sc, sh), 0.f);
            X[(size_t)r * DD + col] = y;
            if (sigout) {
                float s = __fdividef(1.f, 1.f + __expf(-y));
                sigout[(size_t)r * DD + col] = __float2half_rn(s);
            }
            atomicAdd(&sm[g * 64 + cl], y);
        }
    }
    __syncthreads();
    for (int i = threadIdx.x; i < 16384; i += 256) {
        int g = i >> 6;
        int c = c0 + (i & 63);
        float v = sm[i];
        if (c < DD && v != 0.f) atomicAdd(&ssum[g * DD + c], v);
    }
}
__global__ void meanprep_k(const float* __restrict__ ssum, const float* __restrict__ cnts,
                           __half* __restrict__ mH, __half* __restrict__ mE)
{
    int i4 = (blockIdx.x * blockDim.x + threadIdx.x) * 4;
    if (i4 >= NG_ * DD) return;
    int g = i4 / DD;
    float cA1 = fmaxf(cnts[g], 1.f),       cA2 = fmaxf(cnts[512 + g], 1.f);
    float cB1 = fmaxf(cnts[256 + g], 1.f), cB2 = fmaxf(cnts[768 + g], 1.f);
    const float* sh1 = ssum + i4;
    const float* se1 = ssum + 204800 + i4;
    const float* sh2 = ssum + 409600 + i4;
    const float* se2 = ssum + 614400 + i4;
    float4 vh, ve;
    vh.x = sh1[0] / cA1 + sh2[0] / cA2;  ve.x = se1[0] / cB1 + se2[0] / cB2;
    vh.y = sh1[1] / cA1 + sh2[1] / cA2;  ve.y = se1[1] / cB1 + se2[1] / cB2;
    vh.z = sh1[2] / cA1 + sh2[2] / cA2;  ve.z = se1[2] / cB1 + se2[2] / cB2;
    vh.w = sh1[3] / cA1 + sh2[3] / cA2;  ve.w = se1[3] / cB1 + se2[3] / cB2;
    __half2 a = __floats2half2_rn(vh.x, vh.y);
    __half2 b = __floats2half2_rn(vh.z, vh.w);
    *(uint2*)((unsigned short*)mH + i4) = make_uint2(*(uint32_t*)&a, *(uint32_t*)&b);
    a = __floats2half2_rn(ve.x, ve.y);
    b = __floats2half2_rn(ve.z, ve.w);
    *(uint2*)((unsigned short*)mE + i4) = make_uint2(*(uint32_t*)&a, *(uint32_t*)&b);
}
// fused: un = P6+P7+Iu+ind-bias, column stats, then BN+relu applied in-block
__global__ void ucombfinal_k(float* __restrict__ un, const float* __restrict__ P6,
                             const float* __restrict__ P7, const __half* __restrict__ UFIh,
                             const float* __restrict__ cnts, const float* __restrict__ bs,
                             const float* __restrict__ gamma, const float* __restrict__ beta)
{
    __shared__ float ssm[8][32], sqm[8][32];
    __shared__ float sS[32], sQ[32];
    int cl = threadIdx.x & 31, rg = threadIdx.x >> 5;
    int col = blockIdx.x * 32 + cl;
    bool ok = col < DD;
    float s = 0.f, q = 0.f;
    if (ok) {
        float b6 = bs[6 * 800 + col], b7 = bs[7 * 800 + col];
        for (int g = rg; g < NG_; g += 8) {
            float indA = (cnts[g] > 0.f ? 1.f : 0.f) + (cnts[512 + g] > 0.f ? 1.f : 0.f);
            float indB = (cnts[256 + g] > 0.f ? 1.f : 0.f) + (cnts[768 + g] > 0.f ? 1.f : 0.f);
            float v = P6[(size_t)g * DD + col] + P7[(size_t)g * DD + col]
                    + __half2float(UFIh[(size_t)g * 2400 + 1600 + col])
                    + b6 * indA + b7 * indB;
            un[(size_t)g * DD + col] = v;
            s += v; q += v * v;
        }
    }
    ssm[rg][cl] = s; sqm[rg][cl] = q;
    __syncthreads();
    if (rg == 0) {
        float S = 0.f, Q = 0.f;
#pragma unroll
        for (int r = 0; r < 8; r++) { S += ssm[r][cl]; Q += sqm[r][cl]; }
        sS[cl] = S; sQ[cl] = Q;
    }
    __syncthreads();
    if (ok) {
        float m = sS[cl] / (float)NG_;
        float v = sQ[cl] / (float)NG_ - m * m;
        float sc = gamma[col] * rsqrtf(v + 1e-5f);
        float sh = beta[col] - m * sc;
        for (int g = rg; g < NG_; g += 8) {
            float y = un[(size_t)g * DD + col];
            un[(size_t)g * DD + col] = fmaxf(fmaf(y, sc, sh), 0.f);
        }
    }
}

// ---------------------------------------------------------------------------
extern "C" void kernel_launch(void* const* d_in, const int* in_sizes, int n_in,
                              void* d_out, int out_size)
{
    const float* h   = (const float*)d_in[0];
    const float* e   = (const float*)d_in[1];
    const float* h2  = (const float*)d_in[2];
    const float* e2  = (const float*)d_in[3];
    const float* u   = (const float*)d_in[4];
    const float* Ws  = (const float*)d_in[5];
    const float* bs  = (const float*)d_in[6];
    const float* gam = (const float*)d_in[7];
    const float* bet = (const float*)d_in[8];
    const int* ba1 = (const int*)d_in[9];
    const int* ab1 = (const int*)d_in[10];
    const int* ag1 = (const int*)d_in[11];
    const int* bg1 = (const int*)d_in[12];
    const int* ba2 = (const int*)d_in[13];
    const int* ab2 = (const int*)d_in[14];
    const int* ag2 = (const int*)d_in[15];
    const int* bg2 = (const int*)d_in[16];

    float* out = (float*)d_out;
    float* h1n = out;
    float* e1n = out + 16000000;
    float* h2n = out + 35200000;
    float* e2n = out + 51200000;
    float* un  = out + 70400000;

    float* sp = nullptr;
    cudaGetSymbolAddress((void**)&sp, g_scratch);

    __half* P1 = (__half*)(sp + O_P1);
    __half* P2 = (__half*)(sp + O_P2);
    float* SM  = sp + O_SMALL;
    __half* UFIh = (__half*)SM;               // [256][2400] fp16
    float* ssum  = SM + 614400;
    float* cnts  = SM + 1433600;
    float* bnsum = SM + 1434624;
    float* bnsq  = SM + 1438624;
    float* zbias = SM + 1442624;
    __half* mH = (__half*)(SM + 1456224);
    __half* mE = (__half*)(SM + 1661024);
    float* P6 = SM + 1865824;
    float* P7 = SM + 2070624;

    __half* tw   = (__half*)(sp + O_TW);
    __half* thp  = (__half*)(sp + O_THp);
    __half* th2p = (__half*)(sp + O_TH2p);
    __half* tep  = (__half*)(sp + O_TEp);
    __half* te2p = (__half*)(sp + O_TE2p);
    __half* tup  = (__half*)(sp + O_TUp);
    __half* sig1 = tep;
    __half* sig2 = te2p;

    __half* TADE = tw + 0;
    __half* TB1  = tw + 1920000;
    __half* TUFI = tw + 2560000;
    __half* TG   = tw + 4480000;
    __half* TH7  = tw + 5120000;
    __half* TW9  = tw + 5760000;

    const int NH = NA_ * DD, NU = NG_ * DD;

    cudaFuncSetAttribute(hgemm_k<0>, cudaFuncAttributeMaxDynamicSharedMemorySize, SMEM_TOT);
    cudaFuncSetAttribute(hgemm_k<3>, cudaFuncAttributeMaxDynamicSharedMemorySize, SMEM_TOT);
    cudaFuncSetAttribute(hgemm_k<4>, cudaFuncAttributeMaxDynamicSharedMemorySize, SMEM_TOT);
    cudaFuncSetAttribute(hgemm_k<5>, cudaFuncAttributeMaxDynamicSharedMemorySize, SMEM_TOT);
    cudaFuncSetAttribute(bnseg2_k, cudaFuncAttributeMaxDynamicSharedMemorySize, 65536);

    #define NIL6 nullptr, nullptr, nullptr, nullptr, nullptr, nullptr
    #define NILU nullptr, nullptr, nullptr, 0, 0, 0

    // setup + conversions (zero BEFORE counts — no race)
    zero_k<<<(829024 + 255) / 256, 256>>>(ssum, 829024);
    conv_all_k<<<dim3(18750, 4), 256>>>(h, h2, e, e2, thp, th2p, tep, te2p);
    setup_k<<<dim3(200, 5), 256>>>(ag1, bg1, ag2, bg2, cnts, u, tup);
    conv_w_k<<<dim3(25, 25, 10), dim3(32, 8)>>>(Ws, tw);

    // ADE projections -> fp16 P, with UFI fold (mtiles 157,158)
    hgemm_k<4><<<dim3(15, 159, 2), 256, SMEM_TOT>>>(
        thp, th2p, TADE, TADE, bs, bs, 0, 3, 4,
        P1, P2, NA_, 2400,
        nullptr, nullptr, nullptr, nullptr, nullptr, nullptr, nullptr, nullptr, nullptr, NIL6,
        tup, TUFI, UFIh, 2, 5, 8);

    // cross-gate -> thp/th2p reused as t1/t2
    crossconv_k<<<NH / 1024, 256>>>(P1, P2, thp, th2p);

    // e-projection + fused bond update + BN stats
    hgemm_k<3><<<dim3(5, 188, 2), 256, SMEM_TOT>>>(
        tep, te2p, TB1, TB1, bs, bs, 1, 1, 1,
        e1n, e2n, NB_, 800,
        ba1, ba2, bg1, bg2, P1, P2, UFIh,
        bnsum + 0, bnsum + 800, NIL6, NILU);

    // BN(e) apply (prep inline) + segsum + sigmoid emit
    bnseg2_k<<<dim3(13, 12, 2), 256, 65536>>>(e1n, e2n, NB_, bg1, bg2,
                                              bnsum + 0, bnsq + 0, gam, bet, (float)NB_,
                                              ssum + 204800, ssum + 614400, sig1, sig2);

    // fused atom update + cross mix + BN stats (MODE 5)
    hgemm_k<5><<<dim3(5, 157, 2), 256, SMEM_TOT>>>(
        th2p, thp, TW9, TW9, bs, bs, 9, 9, 9,
        h1n, h2n, NA_, 800,
        ba1, ba2, nullptr, nullptr, P1, P2, UFIh,
        bnsum + 1600, bnsum + 2400,
        ab1, ab2, ag1, ag2, sig1, sig2, NILU);

    // BN(h) apply (prep inline) + segsum
    bnseg2_k<<<dim3(13, 12, 2), 256, 65536>>>(h1n, h2n, NA_, ag1, ag2,
                                              bnsum + 1600, bnsq + 1600, gam + 800, bet + 800,
                                              (float)NA_,
                                              ssum + 0, ssum + 409600, nullptr, nullptr);

    // global readout on means
    meanprep_k<<<NU / 1024, 256>>>(ssum, cnts, mH, mE);
    hgemm_k<0><<<dim3(5, 2, 2), 256, SMEM_TOT>>>(
        mH, mE, TG, TH7, zbias, zbias, 0, 0, 0,
        P6, P7, NG_, 800,
        nullptr, nullptr, nullptr, nullptr, nullptr, nullptr, nullptr, nullptr, nullptr, NIL6, NILU);

    // fused combine + stats + BN + relu (single kernel, no extra launch)
    ucombfinal_k<<<25, 256>>>(un, P6, P7, UFIh, cnts, bs, gam + 1600, bet + 1600);
    #undef NIL6
    #undef NILU
}